// round 12
// baseline (speedup 1.0000x reference)
#include <cuda_runtime.h>

// ---------------- problem constants (fixed shapes) ----------------
#define N_SRC1 200000
#define N_DST1 50000
#define N_DST2 10000
#define E1     2000000
#define E2     400000
#define IN_F   128
#define H_F    256
#define N_CLS  47

#define PAD1   50048   // N_DST1 padded to multiple of 128
#define PN     48      // padded layer-2 projected width

// ---------------- scratch (device globals; zero-initialized) ----------------
__device__ int   g_is64;
__device__ int   g_off1[N_DST1 + 1];
__device__ int   g_off2[N_DST2 + 1];
__device__ float g_hneigh1[(size_t)PAD1 * IN_F];   // layer1 mean-aggregated feats
__device__ float g_h[(size_t)PAD1 * H_F];          // layer1 output (relu'd)
__device__ float g_p[(size_t)PAD1 * PN];           // h @ Wneigh2 (projected, padded)
__device__ float g_pagg[(size_t)N_DST2 * PN];      // mean-aggregated p

// ---------------- index dtype detection ----------------
// src1 values are uniform-random in [0, 200000). If int64, every odd 32-bit
// word (high word) is zero; if int32, odd words are random and essentially
// surely nonzero among 128 samples.
__global__ void detect_kernel(const int* __restrict__ src1_raw) {
    if (threadIdx.x == 0) {
        int nz = 0;
        for (int i = 1; i < 256; i += 2) nz |= (src1_raw[i] != 0);
        g_is64 = nz ? 0 : 1;
    }
}

// ---------------- CSR offsets via boundary scatter ----------------
// off[t] = lower_bound(dst, t): thread i owns all t with dst[i-1] < t <= dst[i].
__device__ __forceinline__ void scatter_one(const void* dst, int* off, int E,
                                            int ndst, int i, int is64) {
    int d, p;
    if (is64) {
        d = (int)((const long long*)dst)[i];
        p = (i == 0) ? -1 : (int)((const long long*)dst)[i - 1];
    } else {
        d = ((const int*)dst)[i];
        p = (i == 0) ? -1 : ((const int*)dst)[i - 1];
    }
    for (int t = p + 1; t <= d; ++t) off[t] = i;
    if (i == E - 1)
        for (int t = d + 1; t <= ndst; ++t) off[t] = E;
}

__global__ void offsets_kernel(const void* __restrict__ dst1,
                               const void* __restrict__ dst2) {
    int i = blockIdx.x * blockDim.x + threadIdx.x;
    int is64 = g_is64;
    if (i < E1) scatter_one(dst1, g_off1, E1, N_DST1, i, is64);
    if (i < E2) scatter_one(dst2, g_off2, E2, N_DST2, i, is64);
}

// ---------------- layer-1 aggregation: one warp per dst row ----------------
template <typename IT>
__device__ __forceinline__ void agg1_body(const float* __restrict__ x,
                                          const IT* __restrict__ src,
                                          int row, int lane) {
    int s = g_off1[row], e = g_off1[row + 1];
    float ax = 0.f, ay = 0.f, az = 0.f, aw = 0.f;
    int i = s;
    for (; i + 4 <= e; i += 4) {            // 4 gathers in flight
        int s0 = (int)__ldg(src + i),     s1 = (int)__ldg(src + i + 1);
        int s2 = (int)__ldg(src + i + 2), s3 = (int)__ldg(src + i + 3);
        float4 v0 = __ldg((const float4*)(x + (size_t)s0 * IN_F) + lane);
        float4 v1 = __ldg((const float4*)(x + (size_t)s1 * IN_F) + lane);
        float4 v2 = __ldg((const float4*)(x + (size_t)s2 * IN_F) + lane);
        float4 v3 = __ldg((const float4*)(x + (size_t)s3 * IN_F) + lane);
        ax += (v0.x + v1.x) + (v2.x + v3.x);
        ay += (v0.y + v1.y) + (v2.y + v3.y);
        az += (v0.z + v1.z) + (v2.z + v3.z);
        aw += (v0.w + v1.w) + (v2.w + v3.w);
    }
    for (; i < e; ++i) {
        int s0 = (int)__ldg(src + i);
        float4 v0 = __ldg((const float4*)(x + (size_t)s0 * IN_F) + lane);
        ax += v0.x; ay += v0.y; az += v0.z; aw += v0.w;
    }
    int deg = e - s;
    float sc = 1.0f / (float)(deg > 0 ? deg : 1);
    ((float4*)(g_hneigh1 + (size_t)row * IN_F))[lane] =
        make_float4(ax * sc, ay * sc, az * sc, aw * sc);
}

__global__ __launch_bounds__(256) void agg1_kernel(const float* __restrict__ x,
                                                   const void* __restrict__ srcv) {
    int row = (blockIdx.x * 256 + threadIdx.x) >> 5;
    if (row >= N_DST1) return;
    int lane = threadIdx.x & 31;
    if (g_is64) agg1_body<long long>(x, (const long long*)srcv, row, lane);
    else        agg1_body<int>(x, (const int*)srcv, row, lane);
}

// ---------------- layer-1 fused dual-GEMM + bias + relu ----------------
// g_h[m,n] = relu( x[m,:]@Wself[:,n] + hneigh1[m,:]@Wneigh[:,n] + b1[n] )
// K=256 concat GEMM: chunks 0..7 use (x, Wself), 8..15 use (hneigh1, Wneigh).
// BM=128 BN=64 BK=16, 256 threads, 8m x 4n per thread (acc = 16 u64 f32x2).
// A fragments read as natural m-pairs (LDS.128 -> f32x2 operands directly);
// B tile stored DUPLICATED (b,b) in smem -> zero dup-MOVs in the inner loop.
// 3 CTAs/SM (launch_bounds cap 84 regs) for 24 warps of latency hiding.
__global__ __launch_bounds__(256, 3) void gemm1_kernel(
    const float* __restrict__ x, const float* __restrict__ Wself,
    const float* __restrict__ Wneigh, const float* __restrict__ bias1) {
    __shared__ float As[2][16][136];    // transposed A tiles (k-major), padded
    __shared__ float Bs[2][16][128];    // duplicated B: 64 n -> 128 floats/row

    const int bm = blockIdx.x * 128;
    const int bn = blockIdx.y * 64;
    const int tid = threadIdx.x;
    const int tx = tid & 15;            // n-group: cols bn + tx*4 .. +3
    const int ty = tid >> 4;            // rows bm + ty*8 .. +7
    const int ar = tid >> 1;            // A tile row 0..127
    const int akc = (tid & 1) * 8;      // A k-offset 0 or 8
    const int brow = tid >> 4;          // B k-row 0..15
    const int bcol = (tid & 15) * 4;    // B n-offset (pre-dup)

    unsigned long long acc[4][4];       // [m-pair][n]
    #pragma unroll
    for (int i = 0; i < 4; i++)
        #pragma unroll
        for (int j = 0; j < 4; j++) acc[i][j] = 0ULL;

    // prologue: chunk 0 (x / Wself, k0 = 0) -> buf 0
    {
        const float* ap = x + (size_t)(bm + ar) * IN_F + akc;
        float4 a0 = *(const float4*)ap;
        float4 a1 = *(const float4*)(ap + 4);
        As[0][akc + 0][ar] = a0.x; As[0][akc + 1][ar] = a0.y;
        As[0][akc + 2][ar] = a0.z; As[0][akc + 3][ar] = a0.w;
        As[0][akc + 4][ar] = a1.x; As[0][akc + 5][ar] = a1.y;
        As[0][akc + 6][ar] = a1.z; As[0][akc + 7][ar] = a1.w;
        float4 b = *(const float4*)(Wself + (size_t)brow * H_F + bn + bcol);
        float4* bd = (float4*)&Bs[0][brow][bcol * 2];
        bd[0] = make_float4(b.x, b.x, b.y, b.y);
        bd[1] = make_float4(b.z, b.z, b.w, b.w);
    }
    __syncthreads();

    #pragma unroll 1
    for (int ch = 0; ch < 16; ++ch) {
        int buf = ch & 1;
        float4 pa0, pa1, pb;
        if (ch < 15) {
            int chn = ch + 1;
            const float* Asel = (chn < 8) ? x : g_hneigh1;
            const float* Wsel = (chn < 8) ? Wself : Wneigh;
            int k0 = (chn & 7) * 16;
            const float* ap = Asel + (size_t)(bm + ar) * IN_F + k0 + akc;
            pa0 = *(const float4*)ap;
            pa1 = *(const float4*)(ap + 4);
            pb = *(const float4*)(Wsel + (size_t)(k0 + brow) * H_F + bn + bcol);
        }
        #pragma unroll
        for (int k = 0; k < 16; ++k) {
            // A: 2x LDS.128 -> 4 m-pairs, directly usable as f32x2 operands
            const float* arow = &As[buf][k][ty * 8];
            ulonglong2 am01 = *(const ulonglong2*)arow;
            ulonglong2 am23 = *(const ulonglong2*)(arow + 4);
            unsigned long long am[4] = {am01.x, am01.y, am23.x, am23.y};
            // B: 2x LDS.128 of duplicated pairs -> 4 (b,b) operands, no MOVs
            const ulonglong2* bq = (const ulonglong2*)&Bs[buf][k][tx * 8];
            ulonglong2 b01 = bq[0], b23 = bq[1];
            unsigned long long bb[4] = {b01.x, b01.y, b23.x, b23.y};
            #pragma unroll
            for (int i = 0; i < 4; i++) {
                #pragma unroll
                for (int j = 0; j < 4; j++)
                    asm("fma.rn.f32x2 %0, %1, %2, %0;"
                        : "+l"(acc[i][j]) : "l"(am[i]), "l"(bb[j]));
            }
        }
        if (ch < 15) {
            int nb = buf ^ 1;
            // writes target the buffer whose readers all passed the previous
            // sync -> single sync per chunk is sufficient.
            As[nb][akc + 0][ar] = pa0.x; As[nb][akc + 1][ar] = pa0.y;
            As[nb][akc + 2][ar] = pa0.z; As[nb][akc + 3][ar] = pa0.w;
            As[nb][akc + 4][ar] = pa1.x; As[nb][akc + 5][ar] = pa1.y;
            As[nb][akc + 6][ar] = pa1.z; As[nb][akc + 7][ar] = pa1.w;
            float4* bd = (float4*)&Bs[nb][brow][bcol * 2];
            bd[0] = make_float4(pb.x, pb.x, pb.y, pb.y);
            bd[1] = make_float4(pb.z, pb.z, pb.w, pb.w);
            __syncthreads();
        }
    }

    // epilogue: bias + relu -> g_h. acc[mp][j] = (out[m0][nj], out[m1][nj]).
    float4 bb = *(const float4*)(bias1 + bn + tx * 4);
    #pragma unroll
    for (int mp = 0; mp < 4; ++mp) {
        float lo[4], hi[4];
        #pragma unroll
        for (int j = 0; j < 4; ++j)
            asm("mov.b64 {%0, %1}, %2;" : "=f"(lo[j]), "=f"(hi[j]) : "l"(acc[mp][j]));
        int m0 = bm + ty * 8 + 2 * mp;
        float4 r0, r1;
        r0.x = fmaxf(lo[0] + bb.x, 0.f); r0.y = fmaxf(lo[1] + bb.y, 0.f);
        r0.z = fmaxf(lo[2] + bb.z, 0.f); r0.w = fmaxf(lo[3] + bb.w, 0.f);
        r1.x = fmaxf(hi[0] + bb.x, 0.f); r1.y = fmaxf(hi[1] + bb.y, 0.f);
        r1.z = fmaxf(hi[2] + bb.z, 0.f); r1.w = fmaxf(hi[3] + bb.w, 0.f);
        *(float4*)(g_h + (size_t)m0 * H_F + bn + tx * 4)       = r0;
        *(float4*)(g_h + (size_t)(m0 + 1) * H_F + bn + tx * 4) = r1;
    }
}

// ---------------- small GEMM body: [128 rows, K=256] @ W[256, 47] ----------------
// MODE 0: p = Arows @ W            -> g_p  (padded to PN cols, col 47 = 0)
// MODE 1: out = Arows @ W + g_pagg + b2 -> out (rows < N_DST2, cols < 47)
template <int MODE>
__device__ __forceinline__ void small_gemm_body(
    const float* __restrict__ Arows, const float* __restrict__ W,
    const float* __restrict__ bias2, float* __restrict__ outp, int bm) {
    extern __shared__ float sm[];
    float* sW = sm;                    // [256][49]
    float* As = sm + 256 * 49;         // [2][16][136]

    const int tid = threadIdx.x;
    const int tx = tid & 15;
    const int ty = tid >> 4;
    const int ar = tid >> 1;
    const int akc = (tid & 1) * 8;

    unsigned long long acc[4][3];
    #pragma unroll
    for (int i = 0; i < 4; i++)
        #pragma unroll
        for (int j = 0; j < 3; j++) acc[i][j] = 0ULL;

    for (int idx = tid; idx < 256 * N_CLS; idx += 256) {
        int k = idx / N_CLS, n = idx - k * N_CLS;
        sW[k * 49 + n] = W[idx];
    }
    sW[tid * 49 + 47] = 0.f;

    {
        const float* ap = Arows + (size_t)(bm + ar) * H_F + akc;
        float4 a0 = *(const float4*)ap;
        float4 a1 = *(const float4*)(ap + 4);
        As[(akc + 0) * 136 + ar] = a0.x; As[(akc + 1) * 136 + ar] = a0.y;
        As[(akc + 2) * 136 + ar] = a0.z; As[(akc + 3) * 136 + ar] = a0.w;
        As[(akc + 4) * 136 + ar] = a1.x; As[(akc + 5) * 136 + ar] = a1.y;
        As[(akc + 6) * 136 + ar] = a1.z; As[(akc + 7) * 136 + ar] = a1.w;
    }
    __syncthreads();

    #pragma unroll 1
    for (int ch = 0; ch < 16; ++ch) {
        int buf = ch & 1;
        float4 pa0, pa1;
        if (ch < 15) {
            const float* ap = Arows + (size_t)(bm + ar) * H_F + (ch + 1) * 16 + akc;
            pa0 = *(const float4*)ap;
            pa1 = *(const float4*)(ap + 4);
        }
        const float* Ab = As + buf * (16 * 136);
        #pragma unroll
        for (int k = 0; k < 16; ++k) {
            const float* arow = Ab + k * 136 + ty * 8;
            ulonglong2 p0 = *(const ulonglong2*)(arow + 0);
            ulonglong2 p1 = *(const ulonglong2*)(arow + 4);
            unsigned long long av[4] = {p0.x, p0.y, p1.x, p1.y};
            const float* wr = sW + (ch * 16 + k) * 49 + tx * 3;
            float b0 = wr[0], b1 = wr[1], b2v = wr[2];
            unsigned long long bd0, bd1, bd2;
            asm("mov.b64 %0, {%1, %1};" : "=l"(bd0) : "f"(b0));
            asm("mov.b64 %0, {%1, %1};" : "=l"(bd1) : "f"(b1));
            asm("mov.b64 %0, {%1, %1};" : "=l"(bd2) : "f"(b2v));
            #pragma unroll
            for (int i = 0; i < 4; i++) {
                asm("fma.rn.f32x2 %0, %1, %2, %0;" : "+l"(acc[i][0]) : "l"(av[i]), "l"(bd0));
                asm("fma.rn.f32x2 %0, %1, %2, %0;" : "+l"(acc[i][1]) : "l"(av[i]), "l"(bd1));
                asm("fma.rn.f32x2 %0, %1, %2, %0;" : "+l"(acc[i][2]) : "l"(av[i]), "l"(bd2));
            }
        }
        if (ch < 15) {
            float* Ad = As + (buf ^ 1) * (16 * 136);
            Ad[(akc + 0) * 136 + ar] = pa0.x; Ad[(akc + 1) * 136 + ar] = pa0.y;
            Ad[(akc + 2) * 136 + ar] = pa0.z; Ad[(akc + 3) * 136 + ar] = pa0.w;
            Ad[(akc + 4) * 136 + ar] = pa1.x; Ad[(akc + 5) * 136 + ar] = pa1.y;
            Ad[(akc + 6) * 136 + ar] = pa1.z; Ad[(akc + 7) * 136 + ar] = pa1.w;
            __syncthreads();
        }
    }

    #pragma unroll
    for (int i = 0; i < 4; i++) {
        int m0 = bm + ty * 8 + 2 * i;
        int m1 = m0 + 1;
        float lo[3], hi[3];
        #pragma unroll
        for (int j = 0; j < 3; j++)
            asm("mov.b64 {%0, %1}, %2;" : "=f"(lo[j]), "=f"(hi[j]) : "l"(acc[i][j]));
        if (MODE == 0) {
            #pragma unroll
            for (int j = 0; j < 3; j++) {
                g_p[(size_t)m0 * PN + tx * 3 + j] = lo[j];
                g_p[(size_t)m1 * PN + tx * 3 + j] = hi[j];
            }
        } else {
            if (m0 < N_DST2) {
                #pragma unroll
                for (int j = 0; j < 3; j++) {
                    int n = tx * 3 + j;
                    if (n < N_CLS)
                        outp[m0 * N_CLS + n] =
                            lo[j] + g_pagg[(size_t)m0 * PN + n] + __ldg(bias2 + n);
                }
            }
            if (m1 < N_DST2) {
                #pragma unroll
                for (int j = 0; j < 3; j++) {
                    int n = tx * 3 + j;
                    if (n < N_CLS)
                        outp[m1 * N_CLS + n] =
                            hi[j] + g_pagg[(size_t)m1 * PN + n] + __ldg(bias2 + n);
                }
            }
        }
    }
}

__global__ __launch_bounds__(256) void pgemm_kernel(const float* __restrict__ Wn2) {
    small_gemm_body<0>(g_h, Wn2, nullptr, nullptr, blockIdx.x * 128);
}
__global__ __launch_bounds__(256) void outgemm_kernel(const float* __restrict__ Ws2,
                                                      const float* __restrict__ b2,
                                                      float* __restrict__ out) {
    small_gemm_body<1>(g_h, Ws2, b2, out, blockIdx.x * 128);
}

// ---------------- layer-2 aggregation over projected feats (48 wide) ----------------
template <typename IT>
__device__ __forceinline__ void aggp_body(const IT* __restrict__ src, int g, int t) {
    int s = g_off2[g], e = g_off2[g + 1];
    bool act = (t < PN);
    size_t to = t;
    float acc = 0.f;
    int i = s;
    for (; i + 4 <= e; i += 4) {
        int s0 = (int)__ldg(src + i),     s1 = (int)__ldg(src + i + 1);
        int s2 = (int)__ldg(src + i + 2), s3 = (int)__ldg(src + i + 3);
        if (act) {
            float v0 = __ldg((const float*)g_p + (size_t)s0 * PN + to);
            float v1 = __ldg((const float*)g_p + (size_t)s1 * PN + to);
            float v2 = __ldg((const float*)g_p + (size_t)s2 * PN + to);
            float v3 = __ldg((const float*)g_p + (size_t)s3 * PN + to);
            acc += (v0 + v1) + (v2 + v3);
        }
    }
    for (; i < e; ++i) {
        int s0 = (int)__ldg(src + i);
        if (act) acc += __ldg((const float*)g_p + (size_t)s0 * PN + to);
    }
    int deg = e - s;
    float sc = 1.0f / (float)(deg > 0 ? deg : 1);
    if (act) g_pagg[(size_t)g * PN + t] = acc * sc;
}

__global__ __launch_bounds__(256) void aggp_kernel(const void* __restrict__ srcv) {
    int g = (blockIdx.x * 256 + threadIdx.x) >> 6;
    if (g >= N_DST2) return;
    int t = threadIdx.x & 63;
    if (g_is64) aggp_body<long long>((const long long*)srcv, g, t);
    else        aggp_body<int>((const int*)srcv, g, t);
}

// ---------------- launch ----------------
extern "C" void kernel_launch(void* const* d_in, const int* in_sizes, int n_in,
                              void* d_out, int out_size) {
    const float* x       = (const float*)d_in[0];
    const float* Wself1  = (const float*)d_in[1];
    const float* Wneigh1 = (const float*)d_in[2];
    const float* b1      = (const float*)d_in[3];
    const float* Wself2  = (const float*)d_in[4];
    const float* Wneigh2 = (const float*)d_in[5];
    const float* b2      = (const float*)d_in[6];
    const void*  src1    = d_in[7];
    const void*  dst1    = d_in[8];
    const void*  src2    = d_in[9];
    const void*  dst2    = d_in[10];
    float* out = (float*)d_out;

    const int SMALL_SMEM = (256 * 49 + 2 * 16 * 136) * 4;   // 67584 B
    cudaFuncSetAttribute(pgemm_kernel,
                         cudaFuncAttributeMaxDynamicSharedMemorySize, SMALL_SMEM);
    cudaFuncSetAttribute(outgemm_kernel,
                         cudaFuncAttributeMaxDynamicSharedMemorySize, SMALL_SMEM);

    detect_kernel<<<1, 32>>>((const int*)src1);
    offsets_kernel<<<(E1 + 255) / 256, 256>>>(dst1, dst2);

    agg1_kernel<<<(N_DST1 + 7) / 8, 256>>>(x, src1);

    dim3 g1(PAD1 / 128, H_F / 64);      // 391 x 4 blocks
    gemm1_kernel<<<g1, 256>>>(x, Wself1, Wneigh1, b1);

    pgemm_kernel<<<PAD1 / 128, 256, SMALL_SMEM>>>(Wneigh2);

    aggp_kernel<<<(N_DST2 * 64) / 256, 256>>>(src2);

    outgemm_kernel<<<(N_DST2 + 127) / 128, 256, SMALL_SMEM>>>(Wself2, b2, out);
}

// round 13
// speedup vs baseline: 1.7193x; 1.7193x over previous
#include <cuda_runtime.h>
#include <cuda_bf16.h>

// ---------------- problem constants (fixed shapes) ----------------
#define N_SRC1 200000
#define N_DST1 50000
#define N_DST2 10000
#define E1     2000000
#define E2     400000
#define IN_F   128
#define H_F    256
#define N_CLS  47

#define PAD1   50048   // N_DST1 padded to multiple of 128
#define PN     48      // padded layer-2 projected width

// ---------------- scratch (device globals; zero-initialized) ----------------
__device__ int   g_is64;
__device__ int   g_off1[N_DST1 + 1];
__device__ int   g_off2[N_DST2 + 1];
__device__ float g_hneigh1[(size_t)PAD1 * IN_F];   // layer1 mean-aggregated feats
__device__ float g_h[(size_t)PAD1 * H_F];          // layer1 output (relu'd)
__device__ float g_p[(size_t)PAD1 * PN];           // h @ Wneigh2 (projected, padded)
__device__ float g_pagg[(size_t)N_DST2 * PN];      // mean-aggregated p
// W concat transposed to [n=256][k=256] (k = concat(Wself k, Wneigh k)), bf16 hi/lo
__device__ __align__(16) unsigned short g_bt_hi[256 * 256];
__device__ __align__(16) unsigned short g_bt_lo[256 * 256];

// ---------------- helpers ----------------
__device__ __forceinline__ unsigned smem_u32(const void* p) {
    unsigned a;
    asm("{ .reg .u64 t; cvta.to.shared.u64 t, %1; cvt.u32.u64 %0, t; }"
        : "=r"(a) : "l"(p));
    return a;
}
__device__ __forceinline__ void ldsm_x4(unsigned* r, unsigned addr) {
    asm volatile("ldmatrix.sync.aligned.m8n8.x4.shared.b16 {%0,%1,%2,%3}, [%4];"
                 : "=r"(r[0]), "=r"(r[1]), "=r"(r[2]), "=r"(r[3]) : "r"(addr));
}
__device__ __forceinline__ void mma_bf16(float* c, const unsigned* a,
                                         unsigned b0, unsigned b1) {
    asm volatile(
        "mma.sync.aligned.m16n8k16.row.col.f32.bf16.bf16.f32 "
        "{%0,%1,%2,%3}, {%4,%5,%6,%7}, {%8,%9}, {%0,%1,%2,%3};"
        : "+f"(c[0]), "+f"(c[1]), "+f"(c[2]), "+f"(c[3])
        : "r"(a[0]), "r"(a[1]), "r"(a[2]), "r"(a[3]), "r"(b0), "r"(b1));
}

// ---------------- index dtype detection ----------------
// src1 values are uniform-random in [0, 200000). If int64, every odd 32-bit
// word (high word) is zero; if int32, odd words are random and essentially
// surely nonzero among 128 samples.
__global__ void detect_kernel(const int* __restrict__ src1_raw) {
    if (threadIdx.x == 0) {
        int nz = 0;
        for (int i = 1; i < 256; i += 2) nz |= (src1_raw[i] != 0);
        g_is64 = nz ? 0 : 1;
    }
}

// ---------------- CSR offsets via boundary scatter ----------------
__device__ __forceinline__ void scatter_one(const void* dst, int* off, int E,
                                            int ndst, int i, int is64) {
    int d, p;
    if (is64) {
        d = (int)((const long long*)dst)[i];
        p = (i == 0) ? -1 : (int)((const long long*)dst)[i - 1];
    } else {
        d = ((const int*)dst)[i];
        p = (i == 0) ? -1 : ((const int*)dst)[i - 1];
    }
    for (int t = p + 1; t <= d; ++t) off[t] = i;
    if (i == E - 1)
        for (int t = d + 1; t <= ndst; ++t) off[t] = E;
}

__global__ void offsets_kernel(const void* __restrict__ dst1,
                               const void* __restrict__ dst2) {
    int i = blockIdx.x * blockDim.x + threadIdx.x;
    int is64 = g_is64;
    if (i < E1) scatter_one(dst1, g_off1, E1, N_DST1, i, is64);
    if (i < E2) scatter_one(dst2, g_off2, E2, N_DST2, i, is64);
}

// ---------------- W concat transpose + bf16 hi/lo split ----------------
__global__ void wsplit_kernel(const float* __restrict__ Ws,
                              const float* __restrict__ Wn) {
    int n = blockIdx.x;          // 0..255
    int k = threadIdx.x;         // 0..255
    float v = (k < 128) ? Ws[k * H_F + n] : Wn[(k - 128) * H_F + n];
    __nv_bfloat16 hb = __float2bfloat16(v);
    __nv_bfloat16 lb = __float2bfloat16(v - __bfloat162float(hb));
    g_bt_hi[n * 256 + k] = __bfloat16_as_ushort(hb);
    g_bt_lo[n * 256 + k] = __bfloat16_as_ushort(lb);
}

// ---------------- layer-1 aggregation: one warp per dst row ----------------
template <typename IT>
__device__ __forceinline__ void agg1_body(const float* __restrict__ x,
                                          const IT* __restrict__ src,
                                          int row, int lane) {
    int s = g_off1[row], e = g_off1[row + 1];
    float ax = 0.f, ay = 0.f, az = 0.f, aw = 0.f;
    int i = s;
    for (; i + 4 <= e; i += 4) {            // 4 gathers in flight
        int s0 = (int)__ldg(src + i),     s1 = (int)__ldg(src + i + 1);
        int s2 = (int)__ldg(src + i + 2), s3 = (int)__ldg(src + i + 3);
        float4 v0 = __ldg((const float4*)(x + (size_t)s0 * IN_F) + lane);
        float4 v1 = __ldg((const float4*)(x + (size_t)s1 * IN_F) + lane);
        float4 v2 = __ldg((const float4*)(x + (size_t)s2 * IN_F) + lane);
        float4 v3 = __ldg((const float4*)(x + (size_t)s3 * IN_F) + lane);
        ax += (v0.x + v1.x) + (v2.x + v3.x);
        ay += (v0.y + v1.y) + (v2.y + v3.y);
        az += (v0.z + v1.z) + (v2.z + v3.z);
        aw += (v0.w + v1.w) + (v2.w + v3.w);
    }
    for (; i < e; ++i) {
        int s0 = (int)__ldg(src + i);
        float4 v0 = __ldg((const float4*)(x + (size_t)s0 * IN_F) + lane);
        ax += v0.x; ay += v0.y; az += v0.z; aw += v0.w;
    }
    int deg = e - s;
    float sc = 1.0f / (float)(deg > 0 ? deg : 1);
    ((float4*)(g_hneigh1 + (size_t)row * IN_F))[lane] =
        make_float4(ax * sc, ay * sc, az * sc, aw * sc);
}

__global__ __launch_bounds__(256) void agg1_kernel(const float* __restrict__ x,
                                                   const void* __restrict__ srcv) {
    int row = (blockIdx.x * 256 + threadIdx.x) >> 5;
    if (row >= N_DST1) return;
    int lane = threadIdx.x & 31;
    if (g_is64) agg1_body<long long>(x, (const long long*)srcv, row, lane);
    else        agg1_body<int>(x, (const int*)srcv, row, lane);
}

// ---------------- layer-1 GEMM on classic tensor cores (mma.sync, bf16 split) --
// g_h[m,n] = relu( Acat[m,:] @ Wcat[:,n] + b1[n] ),  Acat = [x | hneigh1].
// 3-term bf16 split: AhBh + AhBl + AlBh, fp32 accumulate (rel err ~1e-5).
// Per CTA: 128m x 128n, 8 warps each m32 x n64, K in 16 chunks of 16.
// smem row stride 40 bf16 (80 B): 80r mod 128 covers 8 distinct 16B banks ->
// conflict-free ldmatrix. hi at cols 0-15, lo at cols 16-31.
__global__ __launch_bounds__(256, 2) void gemm1_kernel(
    const float* __restrict__ x, const float* __restrict__ bias1) {
    __shared__ __align__(16) unsigned short sA[2][128][40];
    __shared__ __align__(16) unsigned short sB[2][128][40];

    const int tid = threadIdx.x, wid = tid >> 5, lane = tid & 31;
    const int bm = blockIdx.x * 128, bn = blockIdx.y * 128;
    const int wm = (wid >> 1) * 32, wn = (wid & 1) * 64;

    float acc[2][8][4];
    #pragma unroll
    for (int i = 0; i < 2; i++)
        #pragma unroll
        for (int j = 0; j < 8; j++)
            #pragma unroll
            for (int q = 0; q < 4; q++) acc[i][j][q] = 0.f;

    const int cr = tid >> 1;            // conversion row / B n-row (0..127)
    const int ck = (tid & 1) * 8;       // k offset 0 or 8

    const unsigned aBase = smem_u32(&sA[0][0][0]);
    const unsigned bBase = smem_u32(&sB[0][0][0]);
    const int lr = lane & 15, lc = (lane >> 4) * 8;
    const unsigned offA = ((unsigned)(wm + lr) * 40 + lc) * 2;
    const unsigned offB = ((unsigned)(wn + lr) * 40 + lc) * 2;
    const unsigned sAst = smem_u32(&sA[0][cr][ck]) - aBase;  // store offsets
    const unsigned sBst = smem_u32(&sB[0][cr][ck]) - bBase;

    // prologue: load chunk 0 into regs
    float4 fa0, fa1; uint4 pbh, pbl;
    {
        const float* ap = x + (size_t)(bm + cr) * IN_F + ck;
        fa0 = __ldg((const float4*)ap);
        fa1 = __ldg((const float4*)ap + 1);
        const size_t bo = (size_t)(bn + cr) * 256 + ck;
        pbh = *(const uint4*)(g_bt_hi + bo);
        pbl = *(const uint4*)(g_bt_lo + bo);
    }
    // convert + store chunk 0 -> buf 0
    {
        float f[8] = {fa0.x, fa0.y, fa0.z, fa0.w, fa1.x, fa1.y, fa1.z, fa1.w};
        unsigned hq[4], lq[4];
        #pragma unroll
        for (int j = 0; j < 4; j++) {
            __nv_bfloat16 h0 = __float2bfloat16(f[2 * j]);
            __nv_bfloat16 h1 = __float2bfloat16(f[2 * j + 1]);
            __nv_bfloat16 l0 = __float2bfloat16(f[2 * j]     - __bfloat162float(h0));
            __nv_bfloat16 l1 = __float2bfloat16(f[2 * j + 1] - __bfloat162float(h1));
            hq[j] = (unsigned)__bfloat16_as_ushort(h0) |
                    ((unsigned)__bfloat16_as_ushort(h1) << 16);
            lq[j] = (unsigned)__bfloat16_as_ushort(l0) |
                    ((unsigned)__bfloat16_as_ushort(l1) << 16);
        }
        *(uint4*)&sA[0][cr][ck]      = make_uint4(hq[0], hq[1], hq[2], hq[3]);
        *(uint4*)&sA[0][cr][16 + ck] = make_uint4(lq[0], lq[1], lq[2], lq[3]);
        *(uint4*)&sB[0][cr][ck]      = pbh;
        *(uint4*)&sB[0][cr][16 + ck] = pbl;
    }
    __syncthreads();

    #pragma unroll 1
    for (int ch = 0; ch < 16; ++ch) {
        const int buf = ch & 1;
        // prefetch chunk ch+1 to regs
        if (ch < 15) {
            const int chn = ch + 1;
            const float* Asel = (chn < 8) ? x : g_hneigh1;
            const int kc = (chn & 7) * 16;
            const float* ap = Asel + (size_t)(bm + cr) * IN_F + kc + ck;
            fa0 = __ldg((const float4*)ap);
            fa1 = __ldg((const float4*)ap + 1);
            const size_t bo = (size_t)(bn + cr) * 256 + chn * 16 + ck;
            pbh = *(const uint4*)(g_bt_hi + bo);
            pbl = *(const uint4*)(g_bt_lo + bo);
        }

        // compute on buf
        {
            const unsigned aB = aBase + buf * 10240;
            const unsigned bB = bBase + buf * 10240;
            unsigned ah[2][4], al[2][4];
            #pragma unroll
            for (int mt = 0; mt < 2; ++mt) {
                ldsm_x4(ah[mt], aB + offA + mt * 1280);
                ldsm_x4(al[mt], aB + offA + mt * 1280 + 32);
            }
            #pragma unroll
            for (int nt2 = 0; nt2 < 4; ++nt2) {
                unsigned bh[4], bl[4];
                ldsm_x4(bh, bB + offB + nt2 * 1280);
                ldsm_x4(bl, bB + offB + nt2 * 1280 + 32);
                #pragma unroll
                for (int mt = 0; mt < 2; ++mt) {
                    float* c0 = acc[mt][nt2 * 2];
                    float* c1 = acc[mt][nt2 * 2 + 1];
                    mma_bf16(c0, ah[mt], bh[0], bh[2]);
                    mma_bf16(c0, ah[mt], bl[0], bl[2]);
                    mma_bf16(c0, al[mt], bh[0], bh[2]);
                    mma_bf16(c1, ah[mt], bh[1], bh[3]);
                    mma_bf16(c1, ah[mt], bl[1], bl[3]);
                    mma_bf16(c1, al[mt], bh[1], bh[3]);
                }
            }
        }

        // convert + store chunk ch+1 -> buf^1 (readers of buf^1 passed the
        // previous sync), then single sync.
        if (ch < 15) {
            const unsigned nb = (buf ^ 1) * 10240u;
            float f[8] = {fa0.x, fa0.y, fa0.z, fa0.w, fa1.x, fa1.y, fa1.z, fa1.w};
            unsigned hq[4], lq[4];
            #pragma unroll
            for (int j = 0; j < 4; j++) {
                __nv_bfloat16 h0 = __float2bfloat16(f[2 * j]);
                __nv_bfloat16 h1 = __float2bfloat16(f[2 * j + 1]);
                __nv_bfloat16 l0 = __float2bfloat16(f[2 * j]     - __bfloat162float(h0));
                __nv_bfloat16 l1 = __float2bfloat16(f[2 * j + 1] - __bfloat162float(h1));
                hq[j] = (unsigned)__bfloat16_as_ushort(h0) |
                        ((unsigned)__bfloat16_as_ushort(h1) << 16);
                lq[j] = (unsigned)__bfloat16_as_ushort(l0) |
                        ((unsigned)__bfloat16_as_ushort(l1) << 16);
            }
            unsigned short* base = &sA[0][0][0];
            *(uint4*)((char*)base + nb + sAst)      = make_uint4(hq[0], hq[1], hq[2], hq[3]);
            *(uint4*)((char*)base + nb + sAst + 32) = make_uint4(lq[0], lq[1], lq[2], lq[3]);
            unsigned short* baseB = &sB[0][0][0];
            *(uint4*)((char*)baseB + nb + sBst)      = pbh;
            *(uint4*)((char*)baseB + nb + sBst + 32) = pbl;
            __syncthreads();
        }
    }

    // epilogue: bias + relu -> g_h
    const int erow = lane >> 2;
    const int ecol = (lane & 3) * 2;
    #pragma unroll
    for (int nt = 0; nt < 8; ++nt) {
        const int col = bn + wn + nt * 8 + ecol;
        const float b0 = __ldg(bias1 + col);
        const float b1 = __ldg(bias1 + col + 1);
        #pragma unroll
        for (int mt = 0; mt < 2; ++mt) {
            const float* c = acc[mt][nt];
            const int r0 = bm + wm + mt * 16 + erow;
            float* p0 = g_h + (size_t)r0 * H_F + col;
            float2 v0 = make_float2(fmaxf(c[0] + b0, 0.f), fmaxf(c[1] + b1, 0.f));
            float2 v1 = make_float2(fmaxf(c[2] + b0, 0.f), fmaxf(c[3] + b1, 0.f));
            *(float2*)p0             = v0;
            *(float2*)(p0 + 8 * H_F) = v1;
        }
    }
}

// ---------------- small GEMM body: [128 rows, K=256] @ W[256, 47] ----------------
// MODE 0: p = Arows @ W            -> g_p  (padded to PN cols, col 47 = 0)
// MODE 1: out = Arows @ W + g_pagg + b2 -> out (rows < N_DST2, cols < 47)
template <int MODE>
__device__ __forceinline__ void small_gemm_body(
    const float* __restrict__ Arows, const float* __restrict__ W,
    const float* __restrict__ bias2, float* __restrict__ outp, int bm) {
    extern __shared__ float sm[];
    float* sW = sm;                    // [256][49]
    float* As = sm + 256 * 49;         // [2][16][136]

    const int tid = threadIdx.x;
    const int tx = tid & 15;
    const int ty = tid >> 4;
    const int ar = tid >> 1;
    const int akc = (tid & 1) * 8;

    unsigned long long acc[4][3];
    #pragma unroll
    for (int i = 0; i < 4; i++)
        #pragma unroll
        for (int j = 0; j < 3; j++) acc[i][j] = 0ULL;

    for (int idx = tid; idx < 256 * N_CLS; idx += 256) {
        int k = idx / N_CLS, n = idx - k * N_CLS;
        sW[k * 49 + n] = W[idx];
    }
    sW[tid * 49 + 47] = 0.f;

    {
        const float* ap = Arows + (size_t)(bm + ar) * H_F + akc;
        float4 a0 = *(const float4*)ap;
        float4 a1 = *(const float4*)(ap + 4);
        As[(akc + 0) * 136 + ar] = a0.x; As[(akc + 1) * 136 + ar] = a0.y;
        As[(akc + 2) * 136 + ar] = a0.z; As[(akc + 3) * 136 + ar] = a0.w;
        As[(akc + 4) * 136 + ar] = a1.x; As[(akc + 5) * 136 + ar] = a1.y;
        As[(akc + 6) * 136 + ar] = a1.z; As[(akc + 7) * 136 + ar] = a1.w;
    }
    __syncthreads();

    #pragma unroll 1
    for (int ch = 0; ch < 16; ++ch) {
        int buf = ch & 1;
        float4 pa0, pa1;
        if (ch < 15) {
            const float* ap = Arows + (size_t)(bm + ar) * H_F + (ch + 1) * 16 + akc;
            pa0 = *(const float4*)ap;
            pa1 = *(const float4*)(ap + 4);
        }
        const float* Ab = As + buf * (16 * 136);
        #pragma unroll
        for (int k = 0; k < 16; ++k) {
            const float* arow = Ab + k * 136 + ty * 8;
            ulonglong2 p0 = *(const ulonglong2*)(arow + 0);
            ulonglong2 p1 = *(const ulonglong2*)(arow + 4);
            unsigned long long av[4] = {p0.x, p0.y, p1.x, p1.y};
            const float* wr = sW + (ch * 16 + k) * 49 + tx * 3;
            float b0 = wr[0], b1 = wr[1], b2v = wr[2];
            unsigned long long bd0, bd1, bd2;
            asm("mov.b64 %0, {%1, %1};" : "=l"(bd0) : "f"(b0));
            asm("mov.b64 %0, {%1, %1};" : "=l"(bd1) : "f"(b1));
            asm("mov.b64 %0, {%1, %1};" : "=l"(bd2) : "f"(b2v));
            #pragma unroll
            for (int i = 0; i < 4; i++) {
                asm("fma.rn.f32x2 %0, %1, %2, %0;" : "+l"(acc[i][0]) : "l"(av[i]), "l"(bd0));
                asm("fma.rn.f32x2 %0, %1, %2, %0;" : "+l"(acc[i][1]) : "l"(av[i]), "l"(bd1));
                asm("fma.rn.f32x2 %0, %1, %2, %0;" : "+l"(acc[i][2]) : "l"(av[i]), "l"(bd2));
            }
        }
        if (ch < 15) {
            float* Ad = As + (buf ^ 1) * (16 * 136);
            Ad[(akc + 0) * 136 + ar] = pa0.x; Ad[(akc + 1) * 136 + ar] = pa0.y;
            Ad[(akc + 2) * 136 + ar] = pa0.z; Ad[(akc + 3) * 136 + ar] = pa0.w;
            Ad[(akc + 4) * 136 + ar] = pa1.x; Ad[(akc + 5) * 136 + ar] = pa1.y;
            Ad[(akc + 6) * 136 + ar] = pa1.z; Ad[(akc + 7) * 136 + ar] = pa1.w;
            __syncthreads();
        }
    }

    #pragma unroll
    for (int i = 0; i < 4; i++) {
        int m0 = bm + ty * 8 + 2 * i;
        int m1 = m0 + 1;
        float lo[3], hi[3];
        #pragma unroll
        for (int j = 0; j < 3; j++)
            asm("mov.b64 {%0, %1}, %2;" : "=f"(lo[j]), "=f"(hi[j]) : "l"(acc[i][j]));
        if (MODE == 0) {
            #pragma unroll
            for (int j = 0; j < 3; j++) {
                g_p[(size_t)m0 * PN + tx * 3 + j] = lo[j];
                g_p[(size_t)m1 * PN + tx * 3 + j] = hi[j];
            }
        } else {
            if (m0 < N_DST2) {
                #pragma unroll
                for (int j = 0; j < 3; j++) {
                    int n = tx * 3 + j;
                    if (n < N_CLS)
                        outp[m0 * N_CLS + n] =
                            lo[j] + g_pagg[(size_t)m0 * PN + n] + __ldg(bias2 + n);
                }
            }
            if (m1 < N_DST2) {
                #pragma unroll
                for (int j = 0; j < 3; j++) {
                    int n = tx * 3 + j;
                    if (n < N_CLS)
                        outp[m1 * N_CLS + n] =
                            hi[j] + g_pagg[(size_t)m1 * PN + n] + __ldg(bias2 + n);
                }
            }
        }
    }
}

__global__ __launch_bounds__(256) void pgemm_kernel(const float* __restrict__ Wn2) {
    small_gemm_body<0>(g_h, Wn2, nullptr, nullptr, blockIdx.x * 128);
}
__global__ __launch_bounds__(256) void outgemm_kernel(const float* __restrict__ Ws2,
                                                      const float* __restrict__ b2,
                                                      float* __restrict__ out) {
    small_gemm_body<1>(g_h, Ws2, b2, out, blockIdx.x * 128);
}

// ---------------- layer-2 aggregation over projected feats (48 wide) ----------------
template <typename IT>
__device__ __forceinline__ void aggp_body(const IT* __restrict__ src, int g, int t) {
    int s = g_off2[g], e = g_off2[g + 1];
    bool act = (t < PN);
    size_t to = t;
    float acc = 0.f;
    int i = s;
    for (; i + 4 <= e; i += 4) {
        int s0 = (int)__ldg(src + i),     s1 = (int)__ldg(src + i + 1);
        int s2 = (int)__ldg(src + i + 2), s3 = (int)__ldg(src + i + 3);
        if (act) {
            float v0 = __ldg((const float*)g_p + (size_t)s0 * PN + to);
            float v1 = __ldg((const float*)g_p + (size_t)s1 * PN + to);
            float v2 = __ldg((const float*)g_p + (size_t)s2 * PN + to);
            float v3 = __ldg((const float*)g_p + (size_t)s3 * PN + to);
            acc += (v0 + v1) + (v2 + v3);
        }
    }
    for (; i < e; ++i) {
        int s0 = (int)__ldg(src + i);
        if (act) acc += __ldg((const float*)g_p + (size_t)s0 * PN + to);
    }
    int deg = e - s;
    float sc = 1.0f / (float)(deg > 0 ? deg : 1);
    if (act) g_pagg[(size_t)g * PN + t] = acc * sc;
}

__global__ __launch_bounds__(256) void aggp_kernel(const void* __restrict__ srcv) {
    int g = (blockIdx.x * 256 + threadIdx.x) >> 6;
    if (g >= N_DST2) return;
    int t = threadIdx.x & 63;
    if (g_is64) aggp_body<long long>((const long long*)srcv, g, t);
    else        aggp_body<int>((const int*)srcv, g, t);
}

// ---------------- launch ----------------
extern "C" void kernel_launch(void* const* d_in, const int* in_sizes, int n_in,
                              void* d_out, int out_size) {
    const float* x       = (const float*)d_in[0];
    const float* Wself1  = (const float*)d_in[1];
    const float* Wneigh1 = (const float*)d_in[2];
    const float* b1      = (const float*)d_in[3];
    const float* Wself2  = (const float*)d_in[4];
    const float* Wneigh2 = (const float*)d_in[5];
    const float* b2      = (const float*)d_in[6];
    const void*  src1    = d_in[7];
    const void*  dst1    = d_in[8];
    const void*  src2    = d_in[9];
    const void*  dst2    = d_in[10];
    float* out = (float*)d_out;

    const int SMALL_SMEM = (256 * 49 + 2 * 16 * 136) * 4;   // 67584 B
    cudaFuncSetAttribute(pgemm_kernel,
                         cudaFuncAttributeMaxDynamicSharedMemorySize, SMALL_SMEM);
    cudaFuncSetAttribute(outgemm_kernel,
                         cudaFuncAttributeMaxDynamicSharedMemorySize, SMALL_SMEM);

    detect_kernel<<<1, 32>>>((const int*)src1);
    offsets_kernel<<<(E1 + 255) / 256, 256>>>(dst1, dst2);
    wsplit_kernel<<<256, 256>>>(Wself1, Wneigh1);

    agg1_kernel<<<(N_DST1 + 7) / 8, 256>>>(x, src1);

    dim3 g1(PAD1 / 128, 2);             // 391 x 2 blocks
    gemm1_kernel<<<g1, 256>>>(x, b1);

    pgemm_kernel<<<PAD1 / 128, 256, SMALL_SMEM>>>(Wneigh2);

    aggp_kernel<<<(N_DST2 * 64) / 256, 256>>>(src2);

    outgemm_kernel<<<(N_DST2 + 127) / 128, 256, SMALL_SMEM>>>(Wself2, b2, out);
}